// round 8
// baseline (speedup 1.0000x reference)
#include <cuda_runtime.h>
#include <cuda_bf16.h>
#include <math.h>
#include <stdint.h>

#define B_SZ 256
#define S_SZ 512
#define V_SZ 50000
#define E_SZ 300
#define H_SZ 1024
#define KP   320

// tiling: 4 mgroups(64 rows) x 32 ntiles(32 cols), full K=1024 per CTA
#define NCTA     128
#define MT       64
#define NTN      32
#define NCHUNK   16                 // 16 chunks of 64 K-cols
#define SW_BYTES   131072           // W: [2 term][32 k32][32 r][64B]
#define SH_BYTES   65536            // h: 4 stages x [2 term][2 sub][64 r][64B]
#define SMEM_RNN   (SW_BYTES + SH_BYTES)

#define TB_STG   24576
#define SMEM_TAB (3 * TB_STG)

// ---------------- scratch ----------------
__device__ __align__(128) __nv_bfloat16 g_h_hi[2][B_SZ * H_SZ];
__device__ __align__(128) __nv_bfloat16 g_h_lo[2][B_SZ * H_SZ];
__device__ __align__(128) __nv_bfloat16 g_w_hi[H_SZ * H_SZ];
__device__ __align__(128) __nv_bfloat16 g_w_lo[H_SZ * H_SZ];
__device__ __align__(128) __nv_bfloat16 g_e_hi[(size_t)V_SZ * KP];
__device__ __align__(128) __nv_bfloat16 g_e_lo[(size_t)V_SZ * KP];
__device__ __align__(128) __nv_bfloat16 g_we_hi[H_SZ * KP];
__device__ __align__(128) __nv_bfloat16 g_we_lo[H_SZ * KP];
__device__ float g_table[(size_t)V_SZ * H_SZ];
__device__ float g_hlast[B_SZ * H_SZ];
__device__ float g_hid[B_SZ * 2 * H_SZ];
__device__ __align__(128) int g_done[128 * 32];    // flag per tile, 128B stride

// ---------------- PTX helpers ----------------
__device__ __forceinline__ uint32_t smem_u32(const void* p) {
    return (uint32_t)__cvta_generic_to_shared(p);
}
__device__ __forceinline__ void cp16(uint32_t dst, const void* src) {
    asm volatile("cp.async.cg.shared.global [%0], [%1], 16;" :: "r"(dst), "l"(src));
}
#define CP_COMMIT() asm volatile("cp.async.commit_group;" ::: "memory")
#define CP_WAIT_G2() asm volatile("cp.async.wait_group 2;" ::: "memory")
#define CP_WAIT_G0() asm volatile("cp.async.wait_group 0;" ::: "memory")
__device__ __forceinline__ void l2pf(const void* p) {
    asm volatile("prefetch.global.L2 [%0];" :: "l"(p));
}
__device__ __forceinline__ int ldvol(const int* p) {
    int v;
    asm volatile("ld.volatile.global.b32 %0, [%1];" : "=r"(v) : "l"(p));
    return v;
}
__device__ __forceinline__ void ldmx4(uint32_t* r, uint32_t addr) {
    asm volatile("ldmatrix.sync.aligned.m8n8.x4.shared.b16 {%0,%1,%2,%3}, [%4];"
        : "=r"(r[0]), "=r"(r[1]), "=r"(r[2]), "=r"(r[3]) : "r"(addr));
}
__device__ __forceinline__ void mma16816(float* d, const uint32_t* a,
                                         const uint32_t b0, const uint32_t b1) {
    asm volatile("mma.sync.aligned.m16n8k16.row.col.f32.bf16.bf16.f32 "
        "{%0,%1,%2,%3}, {%4,%5,%6,%7}, {%8,%9}, {%0,%1,%2,%3};"
        : "+f"(d[0]), "+f"(d[1]), "+f"(d[2]), "+f"(d[3])
        : "r"(a[0]), "r"(a[1]), "r"(a[2]), "r"(a[3]), "r"(b0), "r"(b1));
}

// ---------------- persistent RNN kernel (256 threads, no split-K) ----------------
__global__ void __launch_bounds__(256, 1) rnn_kernel(
    const int* __restrict__ x,
    const float* __restrict__ bias)
{
    extern __shared__ __align__(128) char smem[];
    const uint32_t sw = smem_u32(smem);
    const uint32_t sh = sw + SW_BYTES;

    const int tid  = threadIdx.x;
    const int lane = tid & 31;
    const int wid  = tid >> 5;          // 0..7
    const int wm   = wid >> 1;          // 0..3 -> 16-row band
    const int wn   = wid & 1;           // 0..1 -> 16-col band
    const int cta  = blockIdx.x;
    const int nidx = cta & 31;
    const int midx = cta >> 5;
    const int m0g  = midx * MT;
    const int n0g  = nidx * NTN;
    const int c0   = nidx >> 1;         // rotation: start at own chunk
    int* myflag = g_done + (midx * 32 + nidx) * 32;

    // ---- W slice (32 N-rows x full K) into smem once: 8192 units, 32/thread ----
    {
#pragma unroll
        for (int i = 0; i < 32; i++) {
            int u = tid + i * 256;
            int term = u >> 12;
            int v = u & 4095;
            int ch = v >> 7;            // k32 index 0..31
            int z = v & 127;
            int r = z >> 2, c = z & 3;
            const __nv_bfloat16* src = (term ? g_w_lo : g_w_hi)
                + (size_t)(n0g + r) * H_SZ + ch * 32 + c * 8;
            uint32_t dst = sw + term * 65536 + ch * 2048 + r * 64
                         + ((c ^ ((r >> 1) & 3)) << 4);
            cp16(dst, src);
        }
        CP_COMMIT(); CP_WAIT_G0();
        __syncthreads();
    }

    // ldmatrix lane geometry (warp tile 16M x 16N)
    const int rA = wm * 16 + (lane & 15);
    const int cAadd = lane >> 4;
    const int swzA = (rA >> 1) & 3;
    const int rB = wn * 16 + ((lane >> 4) << 3) + (lane & 7);
    const int cBadd = (lane >> 3) & 1;
    const int swzB = (rB >> 1) & 3;

    float acc[2][4];

    for (int t = 0; t < S_SZ; t++) {
        const __nv_bfloat16* hhi_in = g_h_hi[t & 1];
        const __nv_bfloat16* hlo_in = g_h_lo[t & 1];
        __nv_bfloat16* hhi_out = g_h_hi[(t + 1) & 1];
        __nv_bfloat16* hlo_out = g_h_lo[(t + 1) & 1];

        // flag wait for chunk ach (64 K-cols from producers 2ach, 2ach+1)
        auto wait_ready = [&](int ach) {
            if (t > 0) {
                const int* f0 = g_done + (midx * 32 + 2 * ach) * 32;
                const int* f1 = f0 + 32;
                while (ldvol(f0) < t) __nanosleep(16);
                while (ldvol(f1) < t) __nanosleep(16);
            }
        };
        // issue one 16KB chunk: 1024 units, 4/thread
        auto issue_chunk = [&](int stage, int ach) {
#pragma unroll
            for (int i = 0; i < 4; i++) {
                int u = tid + i * 256;
                int term = u >> 9;
                int v = u & 511;
                int sub = v >> 8;
                int z = v & 255;
                int r = z >> 2, c = z & 3;
                const __nv_bfloat16* src = (term ? hlo_in : hhi_in)
                    + (size_t)(m0g + r) * H_SZ + ach * 64 + sub * 32 + c * 8;
                uint32_t dst = sh + stage * 16384 + term * 8192 + sub * 4096
                             + r * 64 + ((c ^ ((r >> 1) & 3)) << 4);
                cp16(dst, src);
            }
            CP_COMMIT();
        };
        auto compute_chunk = [&](int stage, int ach) {
            const uint32_t hb = sh + stage * 16384;
#pragma unroll
            for (int sub = 0; sub < 2; sub++) {
                const uint32_t hst = hb + sub * 4096;
                const uint32_t wst = sw + (ach * 2 + sub) * 2048;
#pragma unroll
                for (int kkin = 0; kkin < 2; kkin++) {
                    const int cA = ((kkin * 2 + cAadd) ^ swzA) << 4;
                    const int cB = ((kkin * 2 + cBadd) ^ swzB) << 4;
                    uint32_t ahi[4], alo[4], bhi[4], blo[4];
                    ldmx4(ahi, hst + rA * 64 + cA);
                    ldmx4(alo, hst + 8192 + rA * 64 + cA);
                    ldmx4(bhi, wst + rB * 64 + cB);
                    ldmx4(blo, wst + 65536 + rB * 64 + cB);
                    mma16816(acc[0], ahi, bhi[0], bhi[1]);
                    mma16816(acc[1], ahi, bhi[2], bhi[3]);
                    mma16816(acc[0], ahi, blo[0], blo[1]);
                    mma16816(acc[1], ahi, blo[2], blo[3]);
                    mma16816(acc[0], alo, bhi[0], bhi[1]);
                    mma16816(acc[1], alo, bhi[2], bhi[3]);
                }
            }
        };

        // table L2 prefetch (tokens independent of h)
        if (tid < MT) {
            int gr = m0g + tid;
            int tok = x[(size_t)gr * S_SZ + t];
            l2pf(g_table + (size_t)tok * H_SZ + n0g);
        }

#pragma unroll
        for (int j = 0; j < 2; j++)
#pragma unroll
            for (int q = 0; q < 4; q++) acc[j][q] = 0.f;

        // prologue: 3 chunks
#pragma unroll
        for (int p = 0; p < 3; p++) {
            int ach = (c0 + p) & 15;
            wait_ready(ach);
            issue_chunk(p, ach);
        }

        for (int i = 0; i < NCHUNK; i++) {
            CP_WAIT_G2();
            __syncthreads();           // all threads done with chunk i-1's stage
            if (i + 3 < NCHUNK) {      // safe: targets stage (i-1)&3
                int ach = (c0 + i + 3) & 15;
                wait_ready(ach);
                issue_chunk((i + 3) & 3, ach);
            } else {
                CP_COMMIT();           // keep group count uniform
            }
            compute_chunk(i & 3, (c0 + i) & 15);
        }

        // ---- epilogue: + table + bias, tanh, split, store h(t+1) ----
        {
            const int r0 = m0g + wm * 16 + (lane >> 2);
            const int r1 = r0 + 8;
            const int tok0 = x[(size_t)r0 * S_SZ + t];
            const int tok1 = x[(size_t)r1 * S_SZ + t];
            const float* tr0 = g_table + (size_t)tok0 * H_SZ + n0g;
            const float* tr1 = g_table + (size_t)tok1 * H_SZ + n0g;
            const float* bv  = bias + n0g;
#pragma unroll
            for (int jn = 0; jn < 2; jn++) {
                const int c = wn * 16 + jn * 8 + 2 * (lane & 3);
                float2 t0 = *reinterpret_cast<const float2*>(tr0 + c);
                float2 t1 = *reinterpret_cast<const float2*>(tr1 + c);
                float2 bb = *reinterpret_cast<const float2*>(bv + c);
                float v0 = tanhf(acc[jn][0] + t0.x + bb.x);
                float v1 = tanhf(acc[jn][1] + t0.y + bb.y);
                float v2 = tanhf(acc[jn][2] + t1.x + bb.x);
                float v3 = tanhf(acc[jn][3] + t1.y + bb.y);
                __nv_bfloat16 h0 = __float2bfloat16(v0), h1 = __float2bfloat16(v1);
                __nv_bfloat16 h2 = __float2bfloat16(v2), h3 = __float2bfloat16(v3);
                __nv_bfloat162 hi01(h0, h1), hi23(h2, h3);
                __nv_bfloat162 lo01(__float2bfloat16(v0 - __bfloat162float(h0)),
                                    __float2bfloat16(v1 - __bfloat162float(h1)));
                __nv_bfloat162 lo23(__float2bfloat16(v2 - __bfloat162float(h2)),
                                    __float2bfloat16(v3 - __bfloat162float(h3)));
                *reinterpret_cast<__nv_bfloat162*>(hhi_out + (size_t)r0 * H_SZ + n0g + c) = hi01;
                *reinterpret_cast<__nv_bfloat162*>(hlo_out + (size_t)r0 * H_SZ + n0g + c) = lo01;
                *reinterpret_cast<__nv_bfloat162*>(hhi_out + (size_t)r1 * H_SZ + n0g + c) = hi23;
                *reinterpret_cast<__nv_bfloat162*>(hlo_out + (size_t)r1 * H_SZ + n0g + c) = lo23;
            }
        }
        __threadfence();
        __syncthreads();
        if (tid == 0) atomicAdd(myflag, 1);
    }
}

// ---------------- table GEMM on tensor cores ----------------
__global__ void __launch_bounds__(256) table_mma_kernel()
{
    extern __shared__ __align__(128) char smem[];
    const uint32_t sb = smem_u32(smem);
    const int tid  = threadIdx.x;
    const int lane = tid & 31;
    const int wid  = tid >> 5;
    const int wm   = wid >> 1;
    const int wn   = wid & 1;
    const int n0   = blockIdx.x * 64;
    const int m0   = blockIdx.y * 128;

    auto issue_tab = [&](uint32_t sbase, int ch) {
#pragma unroll
        for (int i = 0; i < 6; i++) {
            int u = tid + i * 256;
            if (u < 1024) {
                int term = u >> 9;
                int v = u & 511;
                int r = v >> 2, c = v & 3;
                int gm = m0 + r; if (gm >= V_SZ) gm = V_SZ - 1;
                const __nv_bfloat16* src = (term ? g_e_lo : g_e_hi)
                    + (size_t)gm * KP + ch * 32 + c * 8;
                uint32_t dst = sbase + term * 8192 + r * 64
                             + ((c ^ ((r >> 1) & 3)) << 4);
                cp16(dst, src);
            } else {
                int v = u - 1024;
                int term = v >> 8;
                v &= 255;
                int r = v >> 2, c = v & 3;
                const __nv_bfloat16* src = (term ? g_we_lo : g_we_hi)
                    + (size_t)(n0 + r) * KP + ch * 32 + c * 8;
                uint32_t dst = sbase + 16384 + term * 4096 + r * 64
                             + ((c ^ ((r >> 1) & 3)) << 4);
                cp16(dst, src);
            }
        }
        CP_COMMIT();
    };

    issue_tab(sb + 0 * TB_STG, 0);
    issue_tab(sb + 1 * TB_STG, 1);
    issue_tab(sb + 2 * TB_STG, 2);

    const int rA0 = wm * 32 + (lane & 15);
    const int rA1 = rA0 + 16;
    const int cAadd = lane >> 4;
    const int swzA = (rA0 >> 1) & 3;
    const int rowB0 = wn * 32 + ((lane >> 4) << 3) + (lane & 7);
    const int rowB1 = rowB0 + 16;
    const int cBadd = (lane >> 3) & 1;
    const int swzB = (rowB0 >> 1) & 3;

    float acc[2][4][4];
#pragma unroll
    for (int i = 0; i < 2; i++)
#pragma unroll
        for (int j = 0; j < 4; j++)
#pragma unroll
            for (int q = 0; q < 4; q++) acc[i][j][q] = 0.f;

    const int NCH = KP / 32;
    for (int ch = 0; ch < NCH; ch++) {
        CP_WAIT_G2();
        __syncthreads();
        const uint32_t st = sb + (ch % 3) * TB_STG;
#pragma unroll
        for (int kk = 0; kk < 2; kk++) {
            const int cA = ((kk * 2 + cAadd) ^ swzA) << 4;
            const int cB = ((kk * 2 + cBadd) ^ swzB) << 4;
            uint32_t ahi[8], alo[8], bhi[8], blo[8];
            ldmx4(ahi,     st + rA0 * 64 + cA);
            ldmx4(ahi + 4, st + rA1 * 64 + cA);
            ldmx4(alo,     st + 8192 + rA0 * 64 + cA);
            ldmx4(alo + 4, st + 8192 + rA1 * 64 + cA);
            ldmx4(bhi,     st + 16384 + rowB0 * 64 + cB);
            ldmx4(bhi + 4, st + 16384 + rowB1 * 64 + cB);
            ldmx4(blo,     st + 20480 + rowB0 * 64 + cB);
            ldmx4(blo + 4, st + 20480 + rowB1 * 64 + cB);
#pragma unroll
            for (int i = 0; i < 2; i++)
#pragma unroll
                for (int j = 0; j < 4; j++) {
                    const uint32_t* b = &bhi[(j >> 1) * 4 + (j & 1) * 2];
                    mma16816(acc[i][j], ahi + i * 4, b[0], b[1]);
                }
#pragma unroll
            for (int i = 0; i < 2; i++)
#pragma unroll
                for (int j = 0; j < 4; j++) {
                    const uint32_t* b = &blo[(j >> 1) * 4 + (j & 1) * 2];
                    mma16816(acc[i][j], ahi + i * 4, b[0], b[1]);
                }
#pragma unroll
            for (int i = 0; i < 2; i++)
#pragma unroll
                for (int j = 0; j < 4; j++) {
                    const uint32_t* b = &bhi[(j >> 1) * 4 + (j & 1) * 2];
                    mma16816(acc[i][j], alo + i * 4, b[0], b[1]);
                }
        }
        __syncthreads();
        if (ch + 3 < NCH) issue_tab(sb + (ch % 3) * TB_STG, ch + 3);
        else CP_COMMIT();
    }

#pragma unroll
    for (int i = 0; i < 2; i++) {
        const int r = wm * 32 + i * 16 + (lane >> 2);
#pragma unroll
        for (int j = 0; j < 4; j++) {
            const int c = wn * 32 + j * 8 + 2 * (lane & 3);
            int gm = m0 + r;
            if (gm < V_SZ)
                *reinterpret_cast<float2*>(g_table + (size_t)gm * H_SZ + n0 + c) =
                    make_float2(acc[i][j][0], acc[i][j][1]);
            if (gm + 8 < V_SZ)
                *reinterpret_cast<float2*>(g_table + (size_t)(gm + 8) * H_SZ + n0 + c) =
                    make_float2(acc[i][j][2], acc[i][j][3]);
        }
    }
}

// ---------------- prep / misc ----------------
__global__ void split_w_kernel(const float* __restrict__ W_ih,
                               __nv_bfloat16* __restrict__ whi,
                               __nv_bfloat16* __restrict__ wlo)
{
    int i = blockIdx.x * 256 + threadIdx.x;
    int j = i >> 10, k = i & (H_SZ - 1);
    float w = W_ih[(size_t)j * (E_SZ + H_SZ) + E_SZ + k];
    __nv_bfloat16 hi = __float2bfloat16(w);
    whi[i] = hi;
    wlo[i] = __float2bfloat16(w - __bfloat162float(hi));
}

__global__ void split_e_kernel(const float* __restrict__ embed_W)
{
    size_t id = (size_t)blockIdx.x * 256 + threadIdx.x;
    int row = (int)(id / KP);
    int col = (int)(id - (size_t)row * KP);
    float v = (col < E_SZ) ? embed_W[(size_t)row * E_SZ + col] : 0.f;
    __nv_bfloat16 hi = __float2bfloat16(v);
    g_e_hi[id] = hi;
    g_e_lo[id] = __float2bfloat16(v - __bfloat162float(hi));
}

__global__ void split_we_kernel(const float* __restrict__ W_ih)
{
    int id = blockIdx.x * 256 + threadIdx.x;
    int row = id / KP;
    int col = id - row * KP;
    float v = (col < E_SZ) ? W_ih[(size_t)row * (E_SZ + H_SZ) + col] : 0.f;
    __nv_bfloat16 hi = __float2bfloat16(v);
    g_we_hi[id] = hi;
    g_we_lo[id] = __float2bfloat16(v - __bfloat162float(hi));
}

__global__ void init_kernel(__nv_bfloat16* hi, __nv_bfloat16* lo, int* done) {
    int i = blockIdx.x * 256 + threadIdx.x;
    hi[i] = __float2bfloat16(0.f);
    lo[i] = __float2bfloat16(0.f);
    if (i < 128 * 32) done[i] = 0;
}

__global__ void recon_h_kernel(const __nv_bfloat16* __restrict__ hi,
                               const __nv_bfloat16* __restrict__ lo,
                               float* __restrict__ out) {
    int i = blockIdx.x * 256 + threadIdx.x;
    out[i] = __bfloat162float(hi[i]) + __bfloat162float(lo[i]);
}

// ---------------- SIMT GEMM (MLP L1 only) ----------------
template<int BM, int BN, int BK, int TM, int TN, int MODE>
__global__ void __launch_bounds__(256) gemm_nt(
    const float* __restrict__ A, int lda,
    const float* __restrict__ B, int ldb,
    float* __restrict__ C, int ldc,
    int M, int N, int K,
    const float* __restrict__ bias)
{
    constexpr int BNP = BN + 1;
    __shared__ float As[BM * BK];
    __shared__ float Bs[BK * BNP];
    const int tid = threadIdx.x;
    const int tx = tid % (BN / TN);
    const int ty = tid / (BN / TN);
    const int m0 = blockIdx.y * BM;
    const int n0 = blockIdx.x * BN;
    constexpr int A_LD = (BM * BK / 4) / 256;
    constexpr int B_LD = (BN * BK / 4) / 256;
    float4 aReg[A_LD], bReg[B_LD];
    const int KT = (K + BK - 1) / BK;

    auto loadA = [&](int kt) {
#pragma unroll
        for (int i = 0; i < A_LD; i++) {
            int idx = tid + i * 256;
            int r = idx / (BK / 4), c4 = idx % (BK / 4);
            int gm = m0 + r, gk = kt * BK + c4 * 4;
            aReg[i] = *reinterpret_cast<const float4*>(&A[(size_t)gm * lda + gk]);
        }
    };
    auto loadB = [&](int kt) {
#pragma unroll
        for (int i = 0; i < B_LD; i++) {
            int idx = tid + i * 256;
            int r = idx / (BK / 4), c4 = idx % (BK / 4);
            int gn = n0 + r, gk = kt * BK + c4 * 4;
            bReg[i] = *reinterpret_cast<const float4*>(&B[(size_t)gn * ldb + gk]);
        }
    };
    auto storeA = [&]() {
#pragma unroll
        for (int i = 0; i < A_LD; i++) {
            int idx = tid + i * 256;
            int r = idx / (BK / 4), c4 = idx % (BK / 4);
            *reinterpret_cast<float4*>(&As[r * BK + c4 * 4]) = aReg[i];
        }
    };
    auto storeB = [&]() {
#pragma unroll
        for (int i = 0; i < B_LD; i++) {
            int idx = tid + i * 256;
            int r = idx / (BK / 4), c4 = idx % (BK / 4);
            int kb = c4 * 4;
            float4 v = bReg[i];
            Bs[(kb + 0) * BNP + r] = v.x;
            Bs[(kb + 1) * BNP + r] = v.y;
            Bs[(kb + 2) * BNP + r] = v.z;
            Bs[(kb + 3) * BNP + r] = v.w;
        }
    };

    float acc[TM][TN];
#pragma unroll
    for (int i = 0; i < TM; i++)
#pragma unroll
        for (int j = 0; j < TN; j++) acc[i][j] = 0.f;

    loadA(0); loadB(0); storeA(); storeB();
    __syncthreads();
    for (int kt = 0; kt < KT; kt++) {
        if (kt + 1 < KT) { loadA(kt + 1); loadB(kt + 1); }
#pragma unroll
        for (int kk = 0; kk < BK; kk++) {
            float a[TM], b[TN];
#pragma unroll
            for (int i = 0; i < TM; i++) a[i] = As[(ty * TM + i) * BK + kk];
#pragma unroll
            for (int j = 0; j < TN; j++) b[j] = Bs[kk * BNP + tx * TN + j];
#pragma unroll
            for (int i = 0; i < TM; i++)
#pragma unroll
                for (int j = 0; j < TN; j++)
                    acc[i][j] = fmaf(a[i], b[j], acc[i][j]);
        }
        __syncthreads();
        if (kt + 1 < KT) { storeA(); storeB(); }
        __syncthreads();
    }
#pragma unroll
    for (int i = 0; i < TM; i++) {
        int m = m0 + ty * TM + i;
#pragma unroll
        for (int j = 0; j < TN; j++) {
            int n = n0 + tx * TN + j;
            float v = acc[i][j];
            if (MODE == 2) v = fmaxf(v + bias[n], 0.f);
            C[(size_t)m * ldc + n] = v;
        }
    }
}

__global__ void head2_kernel(const float* __restrict__ hid,
                             const float* __restrict__ W2,
                             const float* __restrict__ b2,
                             float* __restrict__ out)
{
    __shared__ float red[256];
    int b = blockIdx.x;
    float s = 0.f;
    for (int i = threadIdx.x; i < 2 * H_SZ; i += 256)
        s += hid[(size_t)b * 2 * H_SZ + i] * W2[i];
    red[threadIdx.x] = s;
    __syncthreads();
    for (int off = 128; off > 0; off >>= 1) {
        if (threadIdx.x < off) red[threadIdx.x] += red[threadIdx.x + off];
        __syncthreads();
    }
    if (threadIdx.x == 0) out[b] = red[0] + b2[0];
}

// ---------------- host ----------------
extern "C" void kernel_launch(void* const* d_in, const int* in_sizes, int n_in,
                              void* d_out, int out_size)
{
    const int*   x       = (const int*)  d_in[0];
    const float* embed_W = (const float*)d_in[1];
    const float* W_ih    = (const float*)d_in[2];
    const float* b_ih    = (const float*)d_in[3];
    const float* W1      = (const float*)d_in[4];
    const float* b1      = (const float*)d_in[5];
    const float* W2      = (const float*)d_in[6];
    const float* b2      = (const float*)d_in[7];
    float*       out     = (float*)d_out;

    float *hlast, *hid;
    int *done;
    __nv_bfloat16 *hhi0, *hlo0, *whi, *wlo;
    cudaGetSymbolAddress((void**)&hlast, g_hlast);
    cudaGetSymbolAddress((void**)&hid,   g_hid);
    cudaGetSymbolAddress((void**)&done,  g_done);
    {
        __nv_bfloat16* p;
        cudaGetSymbolAddress((void**)&p, g_h_hi); hhi0 = p;
        cudaGetSymbolAddress((void**)&p, g_h_lo); hlo0 = p;
        cudaGetSymbolAddress((void**)&p, g_w_hi); whi = p;
        cudaGetSymbolAddress((void**)&p, g_w_lo); wlo = p;
    }

    static bool attr_done = false;
    if (!attr_done) {
        cudaFuncSetAttribute(rnn_kernel,
            cudaFuncAttributeMaxDynamicSharedMemorySize, SMEM_RNN);
        cudaFuncSetAttribute(table_mma_kernel,
            cudaFuncAttributeMaxDynamicSharedMemorySize, SMEM_TAB);
        attr_done = true;
    }

    init_kernel<<<(B_SZ * H_SZ) / 256, 256>>>(hhi0, hlo0, done);
    split_w_kernel<<<(H_SZ * H_SZ) / 256, 256>>>(W_ih, whi, wlo);
    split_e_kernel<<<(int)(((size_t)V_SZ * KP) / 256), 256>>>(embed_W);
    split_we_kernel<<<(H_SZ * KP) / 256, 256>>>(W_ih);

    table_mma_kernel<<<dim3(H_SZ / 64, (V_SZ + 127) / 128), 256, SMEM_TAB>>>();

    rnn_kernel<<<NCTA, 256, SMEM_RNN>>>(x, b_ih);

    recon_h_kernel<<<(B_SZ * H_SZ) / 256, 256>>>(hhi0, hlo0, hlast);

    gemm_nt<64, 64, 32, 4, 4, 2>
        <<<dim3(2 * H_SZ / 64, B_SZ / 64), 256>>>(
            hlast, H_SZ, W1, H_SZ, hid, 2 * H_SZ,
            B_SZ, 2 * H_SZ, H_SZ, b1);

    head2_kernel<<<B_SZ, 256>>>(hid, W2, b2, out);
}

// round 9
// speedup vs baseline: 2.0904x; 2.0904x over previous
#include <cuda_runtime.h>
#include <cuda_bf16.h>
#include <math.h>
#include <stdint.h>

#define B_SZ 256
#define S_SZ 512
#define V_SZ 50000
#define E_SZ 300
#define H_SZ 1024
#define KP   320

// persistent tiling: 4 mtiles(64) x 8 ntiles(128) x 4 kq(256) = 128 CTAs
#define NCTA     128
#define MT       64
#define NTN      128
#define KQ       256
#define SW_BYTES   131072          // W: [2 term][8 ch][128 r][64B]
#define SH_BYTES   65536           // h: [2 buf][2 term][4 sub][64 r][64B]
#define SMEM_RNN   (SW_BYTES + SH_BYTES)

#define TB_STG   24576
#define SMEM_TAB (3 * TB_STG)

// ---------------- scratch ----------------
__device__ __align__(128) __nv_bfloat16 g_h_hi[2][B_SZ * H_SZ];
__device__ __align__(128) __nv_bfloat16 g_h_lo[2][B_SZ * H_SZ];
__device__ __align__(128) __nv_bfloat16 g_w_hi[H_SZ * H_SZ];
__device__ __align__(128) __nv_bfloat16 g_w_lo[H_SZ * H_SZ];
__device__ __align__(128) __nv_bfloat16 g_e_hi[(size_t)V_SZ * KP];
__device__ __align__(128) __nv_bfloat16 g_e_lo[(size_t)V_SZ * KP];
__device__ __align__(128) __nv_bfloat16 g_we_hi[H_SZ * KP];
__device__ __align__(128) __nv_bfloat16 g_we_lo[H_SZ * KP];
__device__ float g_table[(size_t)V_SZ * H_SZ];
__device__ float g_hlast[B_SZ * H_SZ];
__device__ float g_hid[B_SZ * 2 * H_SZ];
__device__ __align__(128) float g_part[2][32 * 4 * MT * NTN];  // parity-doubled
__device__ __align__(128) int g_cnt[32 * 32];    // 128B stride
__device__ __align__(128) int g_done[32 * 32];   // 128B stride

// ---------------- PTX helpers ----------------
__device__ __forceinline__ uint32_t smem_u32(const void* p) {
    return (uint32_t)__cvta_generic_to_shared(p);
}
__device__ __forceinline__ void cp16(uint32_t dst, const void* src) {
    asm volatile("cp.async.cg.shared.global [%0], [%1], 16;" :: "r"(dst), "l"(src));
}
#define CP_COMMIT() asm volatile("cp.async.commit_group;" ::: "memory")
#define CP_WAIT_G2() asm volatile("cp.async.wait_group 2;" ::: "memory")
#define CP_WAIT_G1() asm volatile("cp.async.wait_group 1;" ::: "memory")
#define CP_WAIT_G0() asm volatile("cp.async.wait_group 0;" ::: "memory")
__device__ __forceinline__ void l2pf(const void* p) {
    asm volatile("prefetch.global.L2 [%0];" :: "l"(p));
}
__device__ __forceinline__ int ld_acq(const int* p) {
    int v;
    asm volatile("ld.acquire.gpu.global.b32 %0, [%1];" : "=r"(v) : "l"(p) : "memory");
    return v;
}
__device__ __forceinline__ void red_rel(int* p) {
    asm volatile("red.release.gpu.global.add.s32 [%0], 1;" :: "l"(p) : "memory");
}
__device__ __forceinline__ void ldmx4(uint32_t* r, uint32_t addr) {
    asm volatile("ldmatrix.sync.aligned.m8n8.x4.shared.b16 {%0,%1,%2,%3}, [%4];"
        : "=r"(r[0]), "=r"(r[1]), "=r"(r[2]), "=r"(r[3]) : "r"(addr));
}
__device__ __forceinline__ void mma16816(float* d, const uint32_t* a,
                                         const uint32_t b0, const uint32_t b1) {
    asm volatile("mma.sync.aligned.m16n8k16.row.col.f32.bf16.bf16.f32 "
        "{%0,%1,%2,%3}, {%4,%5,%6,%7}, {%8,%9}, {%0,%1,%2,%3};"
        : "+f"(d[0]), "+f"(d[1]), "+f"(d[2]), "+f"(d[3])
        : "r"(a[0]), "r"(a[1]), "r"(a[2]), "r"(a[3]), "r"(b0), "r"(b1));
}

// ---------------- persistent RNN kernel (512 threads) ----------------
__global__ void __launch_bounds__(512, 1) rnn_kernel(
    const int* __restrict__ x,
    const float* __restrict__ bias)
{
    extern __shared__ __align__(128) char smem[];
    const uint32_t sw = smem_u32(smem);
    const uint32_t sh = sw + SW_BYTES;

    const int tid  = threadIdx.x;
    const int lane = tid & 31;
    const int wid  = tid >> 5;
    const int wm   = wid >> 2;          // 0..3
    const int wn   = wid & 3;           // 0..3
    const int cta  = blockIdx.x;
    const int kq   = cta & 3;
    const int nidx = (cta >> 2) & 7;
    const int midx = cta >> 5;
    const int m0g  = midx * MT;
    const int n0g  = nidx * NTN;
    const int kbase = kq * KQ;
    const int tile  = midx * 8 + nidx;
    const int feedA = midx * 8 + 2 * kq;
    const int feedB = feedA + 1;

    // ---- W slice into smem (once) ----
    {
#pragma unroll
        for (int i = 0; i < 16; i++) {
            int u = tid + i * 512;
            int term = u >> 12;
            int v = u & 4095;
            int ch = v >> 9;
            int w2 = v & 511;
            int r = w2 >> 2, c = w2 & 3;
            const __nv_bfloat16* src = (term ? g_w_lo : g_w_hi)
                + (size_t)(n0g + r) * H_SZ + kbase + ch * 32 + c * 8;
            uint32_t dst = sw + term * 65536 + ch * 8192 + r * 64
                         + ((c ^ ((r >> 1) & 3)) << 4);
            cp16(dst, src);
        }
        CP_COMMIT(); CP_WAIT_G0();
        __syncthreads();
    }

    // ldmatrix lane geometry (warp tile 16M x 32N)
    const int rA = wm * 16 + (lane & 15);
    const int cAadd = lane >> 4;
    const int swzA = (rA >> 1) & 3;
    const int rowB0 = wn * 32 + ((lane >> 4) << 3) + (lane & 7);
    const int rowB1 = rowB0 + 16;
    const int cBadd = (lane >> 3) & 1;
    const int swzB = (rowB0 >> 1) & 3;

    // issue one 32KB h half (128 K-cols): 2048 units, 4/thread
    auto issue_half = [&](const __nv_bfloat16* hhi_in,
                          const __nv_bfloat16* hlo_in, int buf) {
#pragma unroll
        for (int i = 0; i < 4; i++) {
            int v = tid + i * 512;
            int term = v >> 10;
            int w = v & 1023;
            int sub = w >> 8;
            int z = w & 255;
            int r = z >> 2, c = z & 3;
            const __nv_bfloat16* src = (term ? hlo_in : hhi_in)
                + (size_t)(m0g + r) * H_SZ + kbase + buf * 128 + sub * 32 + c * 8;
            uint32_t dst = sh + buf * 32768 + term * 16384 + sub * 4096
                         + r * 64 + ((c ^ ((r >> 1) & 3)) << 4);
            cp16(dst, src);
        }
        CP_COMMIT();
    };

    float acc[4][4];

    auto compute_half = [&](int buf) {
        const uint32_t hb = sh + buf * 32768;
#pragma unroll
        for (int kk2 = 0; kk2 < 8; kk2++) {
            const int sub = kk2 >> 1, kkin = kk2 & 1;
            const uint32_t hst = hb + sub * 4096;
            const uint32_t wst = sw + (buf * 4 + sub) * 8192;
            const int cA = ((kkin * 2 + cAadd) ^ swzA) << 4;
            const int cB = ((kkin * 2 + cBadd) ^ swzB) << 4;
            uint32_t ahi[4], alo[4], bhi[8], blo[8];
            ldmx4(ahi, hst + rA * 64 + cA);
            ldmx4(alo, hst + 16384 + rA * 64 + cA);
            ldmx4(bhi,     wst + rowB0 * 64 + cB);
            ldmx4(bhi + 4, wst + rowB1 * 64 + cB);
            ldmx4(blo,     wst + 65536 + rowB0 * 64 + cB);
            ldmx4(blo + 4, wst + 65536 + rowB1 * 64 + cB);
#pragma unroll
            for (int j = 0; j < 4; j++) {
                const uint32_t* b = &bhi[(j >> 1) * 4 + (j & 1) * 2];
                mma16816(acc[j], ahi, b[0], b[1]);
            }
#pragma unroll
            for (int j = 0; j < 4; j++) {
                const uint32_t* b = &blo[(j >> 1) * 4 + (j & 1) * 2];
                mma16816(acc[j], ahi, b[0], b[1]);
            }
#pragma unroll
            for (int j = 0; j < 4; j++) {
                const uint32_t* b = &bhi[(j >> 1) * 4 + (j & 1) * 2];
                mma16816(acc[j], alo, b[0], b[1]);
            }
        }
    };

    for (int t = 0; t < S_SZ; t++) {
        const __nv_bfloat16* hhi_in = g_h_hi[t & 1];
        const __nv_bfloat16* hlo_in = g_h_lo[t & 1];
        __nv_bfloat16* hhi_out = g_h_hi[(t + 1) & 1];
        __nv_bfloat16* hlo_out = g_h_lo[(t + 1) & 1];
        float* part = g_part[t & 1];

        // ---- h(t) readiness from feed tiles only (WAR covered by cnt+parity)
        if (t > 0 && tid == 0) {
            const int tgt = 4 * t;
            while (ld_acq(&g_done[feedA * 32]) < tgt) __nanosleep(32);
            while (ld_acq(&g_done[feedB * 32]) < tgt) __nanosleep(32);
        }
        __syncthreads();

        // table L2 prefetch for my 16-row quarter
        if (tid < 16) {
            int gr = m0g + kq * 16 + tid;
            int tok = x[(size_t)gr * S_SZ + t];
            const char* p = (const char*)(g_table + (size_t)tok * H_SZ + n0g);
            l2pf(p); l2pf(p + 128); l2pf(p + 256); l2pf(p + 384);
        }

        issue_half(hhi_in, hlo_in, 0);
        issue_half(hhi_in, hlo_in, 1);

#pragma unroll
        for (int j = 0; j < 4; j++)
#pragma unroll
            for (int q = 0; q < 4; q++) acc[j][q] = 0.f;

        CP_WAIT_G1();
        __syncthreads();
        compute_half(0);
        CP_WAIT_G0();
        __syncthreads();
        compute_half(1);

        // ---- write my partial (parity buffer) ----
        {
            float* pb = part + ((size_t)tile * 4 + kq) * (MT * NTN);
            const int r = wm * 16 + (lane >> 2);
#pragma unroll
            for (int j = 0; j < 4; j++) {
                const int c = wn * 32 + j * 8 + 2 * (lane & 3);
                *reinterpret_cast<float2*>(pb + r * NTN + c) =
                    make_float2(acc[j][0], acc[j][1]);
                *reinterpret_cast<float2*>(pb + (r + 8) * NTN + c) =
                    make_float2(acc[j][2], acc[j][3]);
            }
        }
        __syncthreads();
        if (tid == 0) {
            red_rel(&g_cnt[tile * 32]);
            const int tgt = 4 * (t + 1);
            while (ld_acq(&g_cnt[tile * 32]) < tgt) __nanosleep(32);
        }
        __syncthreads();

        // ---- reduce my 16-row quarter + epilogue ----
        {
            const int rloc = tid >> 5;
            const int c0   = lane * 4;
            const int pr   = kq * 16 + rloc;
            const int gr   = m0g + pr;
            const float* pb = part + (size_t)tile * 4 * (MT * NTN)
                            + pr * NTN + c0;
            float4 s = make_float4(0.f, 0.f, 0.f, 0.f);
#pragma unroll
            for (int q = 0; q < 4; q++) {              // fixed order: deterministic
                float4 a = *reinterpret_cast<const float4*>(pb + q * (MT * NTN));
                s.x += a.x; s.y += a.y; s.z += a.z; s.w += a.w;
            }
            const int tok = x[(size_t)gr * S_SZ + t];
            float4 tv = *reinterpret_cast<const float4*>(
                g_table + (size_t)tok * H_SZ + n0g + c0);
            float4 bv = *reinterpret_cast<const float4*>(bias + n0g + c0);
            float v0 = tanhf(s.x + tv.x + bv.x);
            float v1 = tanhf(s.y + tv.y + bv.y);
            float v2 = tanhf(s.z + tv.z + bv.z);
            float v3 = tanhf(s.w + tv.w + bv.w);
            __nv_bfloat16 h4[4], l4[4];
            h4[0] = __float2bfloat16(v0); l4[0] = __float2bfloat16(v0 - __bfloat162float(h4[0]));
            h4[1] = __float2bfloat16(v1); l4[1] = __float2bfloat16(v1 - __bfloat162float(h4[1]));
            h4[2] = __float2bfloat16(v2); l4[2] = __float2bfloat16(v2 - __bfloat162float(h4[2]));
            h4[3] = __float2bfloat16(v3); l4[3] = __float2bfloat16(v3 - __bfloat162float(h4[3]));
            const size_t ob = (size_t)gr * H_SZ + n0g + c0;
            *reinterpret_cast<uint2*>(hhi_out + ob) = *reinterpret_cast<uint2*>(h4);
            *reinterpret_cast<uint2*>(hlo_out + ob) = *reinterpret_cast<uint2*>(l4);
        }
        __syncthreads();
        if (tid == 0) red_rel(&g_done[tile * 32]);
    }
}

// ---------------- table GEMM on tensor cores ----------------
__global__ void __launch_bounds__(256) table_mma_kernel()
{
    extern __shared__ __align__(128) char smem[];
    const uint32_t sb = smem_u32(smem);
    const int tid  = threadIdx.x;
    const int lane = tid & 31;
    const int wid  = tid >> 5;
    const int wm   = wid >> 1;
    const int wn   = wid & 1;
    const int n0   = blockIdx.x * 64;
    const int m0   = blockIdx.y * 128;

    auto issue_tab = [&](uint32_t sbase, int ch) {
#pragma unroll
        for (int i = 0; i < 6; i++) {
            int u = tid + i * 256;
            if (u < 1024) {
                int term = u >> 9;
                int v = u & 511;
                int r = v >> 2, c = v & 3;
                int gm = m0 + r; if (gm >= V_SZ) gm = V_SZ - 1;
                const __nv_bfloat16* src = (term ? g_e_lo : g_e_hi)
                    + (size_t)gm * KP + ch * 32 + c * 8;
                uint32_t dst = sbase + term * 8192 + r * 64
                             + ((c ^ ((r >> 1) & 3)) << 4);
                cp16(dst, src);
            } else {
                int v = u - 1024;
                int term = v >> 8;
                v &= 255;
                int r = v >> 2, c = v & 3;
                const __nv_bfloat16* src = (term ? g_we_lo : g_we_hi)
                    + (size_t)(n0 + r) * KP + ch * 32 + c * 8;
                uint32_t dst = sbase + 16384 + term * 4096 + r * 64
                             + ((c ^ ((r >> 1) & 3)) << 4);
                cp16(dst, src);
            }
        }
        CP_COMMIT();
    };

    issue_tab(sb + 0 * TB_STG, 0);
    issue_tab(sb + 1 * TB_STG, 1);
    issue_tab(sb + 2 * TB_STG, 2);

    const int rA0 = wm * 32 + (lane & 15);
    const int rA1 = rA0 + 16;
    const int cAadd = lane >> 4;
    const int swzA = (rA0 >> 1) & 3;
    const int rowB0 = wn * 32 + ((lane >> 4) << 3) + (lane & 7);
    const int rowB1 = rowB0 + 16;
    const int cBadd = (lane >> 3) & 1;
    const int swzB = (rowB0 >> 1) & 3;

    float acc[2][4][4];
#pragma unroll
    for (int i = 0; i < 2; i++)
#pragma unroll
        for (int j = 0; j < 4; j++)
#pragma unroll
            for (int q = 0; q < 4; q++) acc[i][j][q] = 0.f;

    const int NCH = KP / 32;
    for (int ch = 0; ch < NCH; ch++) {
        CP_WAIT_G2();
        __syncthreads();
        const uint32_t st = sb + (ch % 3) * TB_STG;
#pragma unroll
        for (int kk = 0; kk < 2; kk++) {
            const int cA = ((kk * 2 + cAadd) ^ swzA) << 4;
            const int cB = ((kk * 2 + cBadd) ^ swzB) << 4;
            uint32_t ahi[8], alo[8], bhi[8], blo[8];
            ldmx4(ahi,     st + rA0 * 64 + cA);
            ldmx4(ahi + 4, st + rA1 * 64 + cA);
            ldmx4(alo,     st + 8192 + rA0 * 64 + cA);
            ldmx4(alo + 4, st + 8192 + rA1 * 64 + cA);
            ldmx4(bhi,     st + 16384 + rowB0 * 64 + cB);
            ldmx4(bhi + 4, st + 16384 + rowB1 * 64 + cB);
            ldmx4(blo,     st + 20480 + rowB0 * 64 + cB);
            ldmx4(blo + 4, st + 20480 + rowB1 * 64 + cB);
#pragma unroll
            for (int i = 0; i < 2; i++)
#pragma unroll
                for (int j = 0; j < 4; j++) {
                    const uint32_t* b = &bhi[(j >> 1) * 4 + (j & 1) * 2];
                    mma16816(acc[i][j], ahi + i * 4, b[0], b[1]);
                }
#pragma unroll
            for (int i = 0; i < 2; i++)
#pragma unroll
                for (int j = 0; j < 4; j++) {
                    const uint32_t* b = &blo[(j >> 1) * 4 + (j & 1) * 2];
                    mma16816(acc[i][j], ahi + i * 4, b[0], b[1]);
                }
#pragma unroll
            for (int i = 0; i < 2; i++)
#pragma unroll
                for (int j = 0; j < 4; j++) {
                    const uint32_t* b = &bhi[(j >> 1) * 4 + (j & 1) * 2];
                    mma16816(acc[i][j], alo + i * 4, b[0], b[1]);
                }
        }
        __syncthreads();
        if (ch + 3 < NCH) issue_tab(sb + (ch % 3) * TB_STG, ch + 3);
        else CP_COMMIT();
    }

#pragma unroll
    for (int i = 0; i < 2; i++) {
        const int r = wm * 32 + i * 16 + (lane >> 2);
#pragma unroll
        for (int j = 0; j < 4; j++) {
            const int c = wn * 32 + j * 8 + 2 * (lane & 3);
            int gm = m0 + r;
            if (gm < V_SZ)
                *reinterpret_cast<float2*>(g_table + (size_t)gm * H_SZ + n0 + c) =
                    make_float2(acc[i][j][0], acc[i][j][1]);
            if (gm + 8 < V_SZ)
                *reinterpret_cast<float2*>(g_table + (size_t)(gm + 8) * H_SZ + n0 + c) =
                    make_float2(acc[i][j][2], acc[i][j][3]);
        }
    }
}

// ---------------- prep / misc ----------------
__global__ void split_w_kernel(const float* __restrict__ W_ih,
                               __nv_bfloat16* __restrict__ whi,
                               __nv_bfloat16* __restrict__ wlo)
{
    int i = blockIdx.x * 256 + threadIdx.x;
    int j = i >> 10, k = i & (H_SZ - 1);
    float w = W_ih[(size_t)j * (E_SZ + H_SZ) + E_SZ + k];
    __nv_bfloat16 hi = __float2bfloat16(w);
    whi[i] = hi;
    wlo[i] = __float2bfloat16(w - __bfloat162float(hi));
}

__global__ void split_e_kernel(const float* __restrict__ embed_W)
{
    size_t id = (size_t)blockIdx.x * 256 + threadIdx.x;
    int row = (int)(id / KP);
    int col = (int)(id - (size_t)row * KP);
    float v = (col < E_SZ) ? embed_W[(size_t)row * E_SZ + col] : 0.f;
    __nv_bfloat16 hi = __float2bfloat16(v);
    g_e_hi[id] = hi;
    g_e_lo[id] = __float2bfloat16(v - __bfloat162float(hi));
}

__global__ void split_we_kernel(const float* __restrict__ W_ih)
{
    int id = blockIdx.x * 256 + threadIdx.x;
    int row = id / KP;
    int col = id - row * KP;
    float v = (col < E_SZ) ? W_ih[(size_t)row * (E_SZ + H_SZ) + col] : 0.f;
    __nv_bfloat16 hi = __float2bfloat16(v);
    g_we_hi[id] = hi;
    g_we_lo[id] = __float2bfloat16(v - __bfloat162float(hi));
}

__global__ void init_kernel(__nv_bfloat16* hi, __nv_bfloat16* lo,
                            int* cnt, int* done) {
    int i = blockIdx.x * 256 + threadIdx.x;
    hi[i] = __float2bfloat16(0.f);
    lo[i] = __float2bfloat16(0.f);
    if (i < 32 * 32) { cnt[i] = 0; done[i] = 0; }
}

__global__ void recon_h_kernel(const __nv_bfloat16* __restrict__ hi,
                               const __nv_bfloat16* __restrict__ lo,
                               float* __restrict__ out) {
    int i = blockIdx.x * 256 + threadIdx.x;
    out[i] = __bfloat162float(hi[i]) + __bfloat162float(lo[i]);
}

// ---------------- SIMT GEMM (MLP L1 only) ----------------
template<int BM, int BN, int BK, int TM, int TN, int MODE>
__global__ void __launch_bounds__(256) gemm_nt(
    const float* __restrict__ A, int lda,
    const float* __restrict__ B, int ldb,
    float* __restrict__ C, int ldc,
    int M, int N, int K,
    const float* __restrict__ bias)
{
    constexpr int BNP = BN + 1;
    __shared__ float As[BM * BK];
    __shared__ float Bs[BK * BNP];
    const int tid = threadIdx.x;
    const int tx = tid % (BN / TN);
    const int ty = tid / (BN / TN);
    const int m0 = blockIdx.y * BM;
    const int n0 = blockIdx.x * BN;
    constexpr int A_LD = (BM * BK / 4) / 256;
    constexpr int B_LD = (BN * BK / 4) / 256;
    float4 aReg[A_LD], bReg[B_LD];
    const int KT = (K + BK - 1) / BK;

    auto loadA = [&](int kt) {
#pragma unroll
        for (int i = 0; i < A_LD; i++) {
            int idx = tid + i * 256;
            int r = idx / (BK / 4), c4 = idx % (BK / 4);
            int gm = m0 + r, gk = kt * BK + c4 * 4;
            aReg[i] = *reinterpret_cast<const float4*>(&A[(size_t)gm * lda + gk]);
        }
    };
    auto loadB = [&](int kt) {
#pragma unroll
        for (int i = 0; i < B_LD; i++) {
            int idx = tid + i * 256;
            int r = idx / (BK / 4), c4 = idx % (BK / 4);
            int gn = n0 + r, gk = kt * BK + c4 * 4;
            bReg[i] = *reinterpret_cast<const float4*>(&B[(size_t)gn * ldb + gk]);
        }
    };
    auto storeA = [&]() {
#pragma unroll
        for (int i = 0; i < A_LD; i++) {
            int idx = tid + i * 256;
            int r = idx / (BK / 4), c4 = idx % (BK / 4);
            *reinterpret_cast<float4*>(&As[r * BK + c4 * 4]) = aReg[i];
        }
    };
    auto storeB = [&]() {
#pragma unroll
        for (int i = 0; i < B_LD; i++) {
            int idx = tid + i * 256;
            int r = idx / (BK / 4), c4 = idx % (BK / 4);
            int kb = c4 * 4;
            float4 v = bReg[i];
            Bs[(kb + 0) * BNP + r] = v.x;
            Bs[(kb + 1) * BNP + r] = v.y;
            Bs[(kb + 2) * BNP + r] = v.z;
            Bs[(kb + 3) * BNP + r] = v.w;
        }
    };

    float acc[TM][TN];
#pragma unroll
    for (int i = 0; i < TM; i++)
#pragma unroll
        for (int j = 0; j < TN; j++) acc[i][j] = 0.f;

    loadA(0); loadB(0); storeA(); storeB();
    __syncthreads();
    for (int kt = 0; kt < KT; kt++) {
        if (kt + 1 < KT) { loadA(kt + 1); loadB(kt + 1); }
#pragma unroll
        for (int kk = 0; kk < BK; kk++) {
            float a[TM], b[TN];
#pragma unroll
            for (int i = 0; i < TM; i++) a[i] = As[(ty * TM + i) * BK + kk];
#pragma unroll
            for (int j = 0; j < TN; j++) b[j] = Bs[kk * BNP + tx * TN + j];
#pragma unroll
            for (int i = 0; i < TM; i++)
#pragma unroll
                for (int j = 0; j < TN; j++)
                    acc[i][j] = fmaf(a[i], b[j], acc[i][j]);
        }
        __syncthreads();
        if (kt + 1 < KT) { storeA(); storeB(); }
        __syncthreads();
    }
#pragma unroll
    for (int i = 0; i < TM; i++) {
        int m = m0 + ty * TM + i;
#pragma unroll
        for (int j = 0; j < TN; j++) {
            int n = n0 + tx * TN + j;
            float v = acc[i][j];
            if (MODE == 2) v = fmaxf(v + bias[n], 0.f);
            C[(size_t)m * ldc + n] = v;
        }
    }
}

__global__ void head2_kernel(const float* __restrict__ hid,
                             const float* __restrict__ W2,
                             const float* __restrict__ b2,
                             float* __restrict__ out)
{
    __shared__ float red[256];
    int b = blockIdx.x;
    float s = 0.f;
    for (int i = threadIdx.x; i < 2 * H_SZ; i += 256)
        s += hid[(size_t)b * 2 * H_SZ + i] * W2[i];
    red[threadIdx.x] = s;
    __syncthreads();
    for (int off = 128; off > 0; off >>= 1) {
        if (threadIdx.x < off) red[threadIdx.x] += red[threadIdx.x + off];
        __syncthreads();
    }
    if (threadIdx.x == 0) out[b] = red[0] + b2[0];
}

// ---------------- host ----------------
extern "C" void kernel_launch(void* const* d_in, const int* in_sizes, int n_in,
                              void* d_out, int out_size)
{
    const int*   x       = (const int*)  d_in[0];
    const float* embed_W = (const float*)d_in[1];
    const float* W_ih    = (const float*)d_in[2];
    const float* b_ih    = (const float*)d_in[3];
    const float* W1      = (const float*)d_in[4];
    const float* b1      = (const float*)d_in[5];
    const float* W2      = (const float*)d_in[6];
    const float* b2      = (const float*)d_in[7];
    float*       out     = (float*)d_out;

    float *hlast, *hid;
    int *cnt, *done;
    __nv_bfloat16 *hhi0, *hlo0, *whi, *wlo;
    cudaGetSymbolAddress((void**)&hlast, g_hlast);
    cudaGetSymbolAddress((void**)&hid,   g_hid);
    cudaGetSymbolAddress((void**)&cnt,   g_cnt);
    cudaGetSymbolAddress((void**)&done,  g_done);
    {
        __nv_bfloat16* p;
        cudaGetSymbolAddress((void**)&p, g_h_hi); hhi0 = p;
        cudaGetSymbolAddress((void**)&p, g_h_lo); hlo0 = p;
        cudaGetSymbolAddress((void**)&p, g_w_hi); whi = p;
        cudaGetSymbolAddress((void**)&p, g_w_lo); wlo = p;
    }

    static bool attr_done = false;
    if (!attr_done) {
        cudaFuncSetAttribute(rnn_kernel,
            cudaFuncAttributeMaxDynamicSharedMemorySize, SMEM_RNN);
        cudaFuncSetAttribute(table_mma_kernel,
            cudaFuncAttributeMaxDynamicSharedMemorySize, SMEM_TAB);
        attr_done = true;
    }

    init_kernel<<<(B_SZ * H_SZ) / 256, 256>>>(hhi0, hlo0, cnt, done);
    split_w_kernel<<<(H_SZ * H_SZ) / 256, 256>>>(W_ih, whi, wlo);
    split_e_kernel<<<(int)(((size_t)V_SZ * KP) / 256), 256>>>(embed_W);
    split_we_kernel<<<(H_SZ * KP) / 256, 256>>>(W_ih);

    table_mma_kernel<<<dim3(H_SZ / 64, (V_SZ + 127) / 128), 256, SMEM_TAB>>>();

    rnn_kernel<<<NCTA, 512, SMEM_RNN>>>(x, b_ih);

    recon_h_kernel<<<(B_SZ * H_SZ) / 256, 256>>>(hhi0, hlo0, hlast);

    gemm_nt<64, 64, 32, 4, 4, 2>
        <<<dim3(2 * H_SZ / 64, B_SZ / 64), 256>>>(
            hlast, H_SZ, W1, H_SZ, hid, 2 * H_SZ,
            B_SZ, 2 * H_SZ, H_SZ, b1);

    head2_kernel<<<B_SZ, 256>>>(hid, W2, b2, out);
}